// round 10
// baseline (speedup 1.0000x reference)
#include <cuda_runtime.h>
#include <math.h>

// Problem constants (fixed by the dataset)
#define BB   32
#define TT   2048
#define DD   1024
#define AA   1024
#define MTOT (BB * TT)   // 65536 rows of the big GEMM

// ---------------------------------------------------------------------------
// Scratch (static __device__ arrays: allocation-free, graph-capture safe)
// ---------------------------------------------------------------------------
__device__ float g_ws[BB * AA];        // W_a_s : [B, A]
__device__ float g_part[8 * MTOT];     // per-(n-block) score partials, deterministic
__device__ float g_esc[MTOT];          // exp(scores)
__device__ float g_invden[BB];         // 1 / sum_t exp(scores)

// ---------------------------------------------------------------------------
// Packed fp32x2 helpers (Blackwell FFMA2 — only reachable via PTX)
// ---------------------------------------------------------------------------
__device__ __forceinline__ unsigned long long pk2(float lo, float hi) {
    unsigned long long r;
    asm("mov.b64 %0, {%1, %2};" : "=l"(r) : "f"(lo), "f"(hi));
    return r;
}
__device__ __forceinline__ void up2(unsigned long long v, float& lo, float& hi) {
    asm("mov.b64 {%0, %1}, %2;" : "=f"(lo), "=f"(hi) : "l"(v));
}
__device__ __forceinline__ void fma2(unsigned long long& d,
                                     unsigned long long a,
                                     unsigned long long b) {
    asm("fma.rn.f32x2 %0, %1, %2, %3;" : "=l"(d) : "l"(a), "l"(b), "l"(d));
}

// ---------------------------------------------------------------------------
// Kernel 0: g_ws[b][a] = sum_d s[b][d] * W_a[d][a]   (tiny GEMM, 67 MFLOP)
// grid (8, 32), block 128
// ---------------------------------------------------------------------------
__global__ void ws_kernel(const float* __restrict__ s, const float* __restrict__ W) {
    __shared__ float ss[DD];
    const int b = blockIdx.y;
    const int a = blockIdx.x * 128 + threadIdx.x;

    for (int i = threadIdx.x; i < DD; i += 128) ss[i] = s[b * DD + i];
    __syncthreads();

    float a0 = 0.f, a1 = 0.f, a2 = 0.f, a3 = 0.f;
    for (int d = 0; d < DD; d += 4) {
        a0 += ss[d + 0] * W[(size_t)(d + 0) * AA + a];
        a1 += ss[d + 1] * W[(size_t)(d + 1) * AA + a];
        a2 += ss[d + 2] * W[(size_t)(d + 2) * AA + a];
        a3 += ss[d + 3] * W[(size_t)(d + 3) * AA + a];
    }
    g_ws[b * AA + a] = (a0 + a1) + (a2 + a3);
}

// ---------------------------------------------------------------------------
// Kernel 1: fused GEMM + tanh + dot(v) -> per-n-block score partials.
//
// Tile: BM=128 x BN=128 x BK=16, 256 threads, 8x8 micro-tile per thread,
// accumulated in f32x2 pairs via fma.rn.f32x2 (2 FMAs per issue slot).
// Each block owns rows [m0, m0+128) (all inside one batch b since 128 | T)
// and columns [n0, n0+128). After the K loop it collapses its tile through
// tanh(acc + ws)·v into one partial per row and writes g_part[nb][m]
// (exactly one writer per slot -> deterministic, no atomics, no zero-init).
//
// grid (8, 512), block 256
// ---------------------------------------------------------------------------
__global__ void __launch_bounds__(256, 2)
score_gemm_kernel(const float* __restrict__ h,
                  const float* __restrict__ U,
                  const float* __restrict__ v) {
    __shared__ __align__(16) float As[16][132];   // [k][m], padded: STS 2-way max
    __shared__ __align__(16) float Bs[16][128];   // [k][n]

    const int tid = threadIdx.x;
    const int nb  = blockIdx.x;          // 0..7
    const int n0  = nb * 128;
    const int m0  = blockIdx.y * 128;

    // global->shared load mapping
    const int arow = tid >> 2;           // 0..63
    const int acol = (tid & 3) << 2;     // 0,4,8,12
    const int brow = tid >> 5;           // 0..7
    const int bcol = (tid & 31) << 2;    // 0..124

    // compute mapping: 16x16 thread grid, 8x8 micro-tile (4+4 split)
    const int ty = tid >> 4;             // 0..15 -> M
    const int tx = tid & 15;             // 0..15 -> N

    const float* hA = h + (size_t)m0 * DD;

    unsigned long long acc[8][4];
#pragma unroll
    for (int i = 0; i < 8; i++)
#pragma unroll
        for (int j = 0; j < 4; j++) acc[i][j] = 0ull;

    for (int kt = 0; kt < DD; kt += 16) {
        // issue global loads first (latency overlapped with prior compute)
        float4 av0 = *reinterpret_cast<const float4*>(&hA[(size_t)arow        * DD + kt + acol]);
        float4 av1 = *reinterpret_cast<const float4*>(&hA[(size_t)(arow + 64) * DD + kt + acol]);
        float4 bv0 = *reinterpret_cast<const float4*>(&U[(size_t)(kt + brow)     * AA + n0 + bcol]);
        float4 bv1 = *reinterpret_cast<const float4*>(&U[(size_t)(kt + brow + 8) * AA + n0 + bcol]);

        __syncthreads();   // previous tile fully consumed
        As[acol + 0][arow] = av0.x;  As[acol + 1][arow] = av0.y;
        As[acol + 2][arow] = av0.z;  As[acol + 3][arow] = av0.w;
        As[acol + 0][arow + 64] = av1.x;  As[acol + 1][arow + 64] = av1.y;
        As[acol + 2][arow + 64] = av1.z;  As[acol + 3][arow + 64] = av1.w;
        *reinterpret_cast<float4*>(&Bs[brow][bcol])     = bv0;
        *reinterpret_cast<float4*>(&Bs[brow + 8][bcol]) = bv1;
        __syncthreads();

#pragma unroll
        for (int k = 0; k < 16; k++) {
            float4 a0 = *reinterpret_cast<const float4*>(&As[k][ty * 4]);
            float4 a1 = *reinterpret_cast<const float4*>(&As[k][ty * 4 + 64]);
            float4 b0 = *reinterpret_cast<const float4*>(&Bs[k][tx * 4]);
            float4 b1 = *reinterpret_cast<const float4*>(&Bs[k][tx * 4 + 64]);

            unsigned long long bb[4];
            bb[0] = pk2(b0.x, b0.y);  bb[1] = pk2(b0.z, b0.w);
            bb[2] = pk2(b1.x, b1.y);  bb[3] = pk2(b1.z, b1.w);

            float am[8] = {a0.x, a0.y, a0.z, a0.w, a1.x, a1.y, a1.z, a1.w};
#pragma unroll
            for (int i = 0; i < 8; i++) {
                unsigned long long ad = pk2(am[i], am[i]);
#pragma unroll
                for (int j = 0; j < 4; j++) fma2(acc[i][j], ad, bb[j]);
            }
        }
    }

    // ---- epilogue: tanh(acc + ws) . v -> per-row partial, reduce over tx ----
    const int b = m0 >> 11;              // T = 2048, BM=128 divides T
    const float* wsrow = g_ws + b * AA + n0;

    float wsv[8], vv[8];
#pragma unroll
    for (int jj = 0; jj < 8; jj++) {
        // columns: jj<4 -> tx*4+jj ; jj>=4 -> tx*4+64+(jj-4)
        const int col = (jj < 4) ? (tx * 4 + jj) : (tx * 4 + 60 + jj);
        wsv[jj] = wsrow[col];
        vv[jj]  = v[n0 + col];
    }

#pragma unroll
    for (int i = 0; i < 8; i++) {
        float ssum = 0.f;
#pragma unroll
        for (int j2 = 0; j2 < 4; j2++) {
            float lo, hi;
            up2(acc[i][j2], lo, hi);
            ssum += vv[2 * j2 + 0] * tanhf(lo + wsv[2 * j2 + 0]);
            ssum += vv[2 * j2 + 1] * tanhf(hi + wsv[2 * j2 + 1]);
        }
        // reduce across the 16 tx lanes (lane = (ty&1)*16 + tx; xor<=8 stays in group)
#pragma unroll
        for (int off = 8; off > 0; off >>= 1)
            ssum += __shfl_xor_sync(0xffffffffu, ssum, off);

        if (tx == 0) {
            const int row = (i < 4) ? (ty * 4 + i) : (ty * 4 + 60 + i);
            g_part[nb * MTOT + m0 + row] = ssum;   // single writer per slot
        }
    }
}

// ---------------------------------------------------------------------------
// Kernel 2: scores = sum over 8 partials; e = exp(scores) (raw, per reference);
//           g_invden[b] = 1/sum_t e.   grid 32, block 256
// ---------------------------------------------------------------------------
__global__ void softmax_kernel() {
    const int b = blockIdx.x;
    __shared__ float red[256];

    float local = 0.f;
    for (int t = threadIdx.x; t < TT; t += 256) {
        const int m = b * TT + t;
        float sc = 0.f;
#pragma unroll
        for (int p = 0; p < 8; p++) sc += g_part[p * MTOT + m];
        const float e = expf(sc);
        g_esc[m] = e;
        local += e;
    }
    red[threadIdx.x] = local;
    __syncthreads();
    for (int s = 128; s > 0; s >>= 1) {
        if (threadIdx.x < s) red[threadIdx.x] += red[threadIdx.x + s];
        __syncthreads();
    }
    if (threadIdx.x == 0) g_invden[b] = 1.0f / red[0];
}

// ---------------------------------------------------------------------------
// Kernel 3: c[b][d] = (sum_t e[b][t] * h[b][t][d]) * invden[b]
// grid (4, 32), block 256 — memory-bound, one full coalesced pass over h.
// ---------------------------------------------------------------------------
__global__ void ctx_kernel(const float* __restrict__ h, float* __restrict__ out) {
    const int b = blockIdx.y;
    const int d = blockIdx.x * 256 + threadIdx.x;
    __shared__ float w[128];

    const float* hb = h + (size_t)b * TT * DD;
    float acc0 = 0.f, acc1 = 0.f;

    for (int t0 = 0; t0 < TT; t0 += 128) {
        __syncthreads();
        if (threadIdx.x < 128) w[threadIdx.x] = g_esc[b * TT + t0 + threadIdx.x];
        __syncthreads();
#pragma unroll 16
        for (int i = 0; i < 128; i += 2) {
            acc0 += w[i + 0] * hb[(size_t)(t0 + i + 0) * DD + d];
            acc1 += w[i + 1] * hb[(size_t)(t0 + i + 1) * DD + d];
        }
    }
    out[b * DD + d] = (acc0 + acc1) * g_invden[b];
}

// ---------------------------------------------------------------------------
// Launch (graph-capturable: kernels only, default stream, no allocs/syncs)
// Inputs per metadata order: s, h, W_a, U_a, v_a (all float32)
// ---------------------------------------------------------------------------
extern "C" void kernel_launch(void* const* d_in, const int* in_sizes, int n_in,
                              void* d_out, int out_size) {
    const float* s  = (const float*)d_in[0];
    const float* h  = (const float*)d_in[1];
    const float* Wa = (const float*)d_in[2];
    const float* Ua = (const float*)d_in[3];
    const float* va = (const float*)d_in[4];
    float* out = (float*)d_out;

    ws_kernel       <<<dim3(8, 32),  128>>>(s, Wa);
    score_gemm_kernel<<<dim3(8, 512), 256>>>(h, Ua, va);
    softmax_kernel  <<<32,           256>>>();
    ctx_kernel      <<<dim3(4, 32),  256>>>(h, out);
}

// round 11
// speedup vs baseline: 1.0010x; 1.0010x over previous
#include <cuda_runtime.h>
#include <math.h>

// Problem constants (fixed by the dataset)
#define BB   32
#define TT   2048
#define DD   1024
#define AA   1024
#define MTOT (BB * TT)   // 65536 rows of the big GEMM

// ---------------------------------------------------------------------------
// Scratch (static __device__ arrays: allocation-free, graph-capture safe)
// ---------------------------------------------------------------------------
__device__ float g_ws[BB * AA];        // W_a_s : [B, A]
__device__ float g_part[8 * MTOT];     // per-(n-block) score partials, deterministic
__device__ float g_esc[MTOT];          // exp(scores)
__device__ float g_invden[BB];         // 1 / sum_t exp(scores)

// ---------------------------------------------------------------------------
// Packed fp32x2 helpers (Blackwell FFMA2 — only reachable via PTX)
// ---------------------------------------------------------------------------
__device__ __forceinline__ unsigned long long pk2(float lo, float hi) {
    unsigned long long r;
    asm("mov.b64 %0, {%1, %2};" : "=l"(r) : "f"(lo), "f"(hi));
    return r;
}
__device__ __forceinline__ void up2(unsigned long long v, float& lo, float& hi) {
    asm("mov.b64 {%0, %1}, %2;" : "=f"(lo), "=f"(hi) : "l"(v));
}
__device__ __forceinline__ void fma2(unsigned long long& d,
                                     unsigned long long a,
                                     unsigned long long b) {
    asm("fma.rn.f32x2 %0, %1, %2, %3;" : "=l"(d) : "l"(a), "l"(b), "l"(d));
}

// ---------------------------------------------------------------------------
// Kernel 0: g_ws[b][a] = sum_d s[b][d] * W_a[d][a]   (tiny GEMM, 67 MFLOP)
// grid (8, 32), block 128
// ---------------------------------------------------------------------------
__global__ void ws_kernel(const float* __restrict__ s, const float* __restrict__ W) {
    __shared__ float ss[DD];
    const int b = blockIdx.y;
    const int a = blockIdx.x * 128 + threadIdx.x;

    for (int i = threadIdx.x; i < DD; i += 128) ss[i] = s[b * DD + i];
    __syncthreads();

    float a0 = 0.f, a1 = 0.f, a2 = 0.f, a3 = 0.f;
    for (int d = 0; d < DD; d += 4) {
        a0 += ss[d + 0] * W[(size_t)(d + 0) * AA + a];
        a1 += ss[d + 1] * W[(size_t)(d + 1) * AA + a];
        a2 += ss[d + 2] * W[(size_t)(d + 2) * AA + a];
        a3 += ss[d + 3] * W[(size_t)(d + 3) * AA + a];
    }
    g_ws[b * AA + a] = (a0 + a1) + (a2 + a3);
}

// ---------------------------------------------------------------------------
// Kernel 1: fused GEMM + tanh + dot(v) -> per-n-block score partials.
//
// Tile: BM=128 x BN=128 x BK=16, 256 threads, 8x8 micro-tile per thread,
// accumulated in f32x2 pairs via fma.rn.f32x2 (2 FMAs per issue slot).
// Each block owns rows [m0, m0+128) (all inside one batch b since 128 | T)
// and columns [n0, n0+128). After the K loop it collapses its tile through
// tanh(acc + ws)·v into one partial per row and writes g_part[nb][m]
// (exactly one writer per slot -> deterministic, no atomics, no zero-init).
//
// grid (8, 512), block 256
// ---------------------------------------------------------------------------
__global__ void __launch_bounds__(256, 2)
score_gemm_kernel(const float* __restrict__ h,
                  const float* __restrict__ U,
                  const float* __restrict__ v) {
    __shared__ __align__(16) float As[16][132];   // [k][m], padded: STS 2-way max
    __shared__ __align__(16) float Bs[16][128];   // [k][n]

    const int tid = threadIdx.x;
    const int nb  = blockIdx.x;          // 0..7
    const int n0  = nb * 128;
    const int m0  = blockIdx.y * 128;

    // global->shared load mapping
    const int arow = tid >> 2;           // 0..63
    const int acol = (tid & 3) << 2;     // 0,4,8,12
    const int brow = tid >> 5;           // 0..7
    const int bcol = (tid & 31) << 2;    // 0..124

    // compute mapping: 16x16 thread grid, 8x8 micro-tile (4+4 split)
    const int ty = tid >> 4;             // 0..15 -> M
    const int tx = tid & 15;             // 0..15 -> N

    const float* hA = h + (size_t)m0 * DD;

    unsigned long long acc[8][4];
#pragma unroll
    for (int i = 0; i < 8; i++)
#pragma unroll
        for (int j = 0; j < 4; j++) acc[i][j] = 0ull;

    for (int kt = 0; kt < DD; kt += 16) {
        // issue global loads first (latency overlapped with prior compute)
        float4 av0 = *reinterpret_cast<const float4*>(&hA[(size_t)arow        * DD + kt + acol]);
        float4 av1 = *reinterpret_cast<const float4*>(&hA[(size_t)(arow + 64) * DD + kt + acol]);
        float4 bv0 = *reinterpret_cast<const float4*>(&U[(size_t)(kt + brow)     * AA + n0 + bcol]);
        float4 bv1 = *reinterpret_cast<const float4*>(&U[(size_t)(kt + brow + 8) * AA + n0 + bcol]);

        __syncthreads();   // previous tile fully consumed
        As[acol + 0][arow] = av0.x;  As[acol + 1][arow] = av0.y;
        As[acol + 2][arow] = av0.z;  As[acol + 3][arow] = av0.w;
        As[acol + 0][arow + 64] = av1.x;  As[acol + 1][arow + 64] = av1.y;
        As[acol + 2][arow + 64] = av1.z;  As[acol + 3][arow + 64] = av1.w;
        *reinterpret_cast<float4*>(&Bs[brow][bcol])     = bv0;
        *reinterpret_cast<float4*>(&Bs[brow + 8][bcol]) = bv1;
        __syncthreads();

#pragma unroll
        for (int k = 0; k < 16; k++) {
            float4 a0 = *reinterpret_cast<const float4*>(&As[k][ty * 4]);
            float4 a1 = *reinterpret_cast<const float4*>(&As[k][ty * 4 + 64]);
            float4 b0 = *reinterpret_cast<const float4*>(&Bs[k][tx * 4]);
            float4 b1 = *reinterpret_cast<const float4*>(&Bs[k][tx * 4 + 64]);

            unsigned long long bb[4];
            bb[0] = pk2(b0.x, b0.y);  bb[1] = pk2(b0.z, b0.w);
            bb[2] = pk2(b1.x, b1.y);  bb[3] = pk2(b1.z, b1.w);

            float am[8] = {a0.x, a0.y, a0.z, a0.w, a1.x, a1.y, a1.z, a1.w};
#pragma unroll
            for (int i = 0; i < 8; i++) {
                unsigned long long ad = pk2(am[i], am[i]);
#pragma unroll
                for (int j = 0; j < 4; j++) fma2(acc[i][j], ad, bb[j]);
            }
        }
    }

    // ---- epilogue: tanh(acc + ws) . v -> per-row partial, reduce over tx ----
    const int b = m0 >> 11;              // T = 2048, BM=128 divides T
    const float* wsrow = g_ws + b * AA + n0;

    float wsv[8], vv[8];
#pragma unroll
    for (int jj = 0; jj < 8; jj++) {
        // columns: jj<4 -> tx*4+jj ; jj>=4 -> tx*4+64+(jj-4)
        const int col = (jj < 4) ? (tx * 4 + jj) : (tx * 4 + 60 + jj);
        wsv[jj] = wsrow[col];
        vv[jj]  = v[n0 + col];
    }

#pragma unroll
    for (int i = 0; i < 8; i++) {
        float ssum = 0.f;
#pragma unroll
        for (int j2 = 0; j2 < 4; j2++) {
            float lo, hi;
            up2(acc[i][j2], lo, hi);
            ssum += vv[2 * j2 + 0] * tanhf(lo + wsv[2 * j2 + 0]);
            ssum += vv[2 * j2 + 1] * tanhf(hi + wsv[2 * j2 + 1]);
        }
        // reduce across the 16 tx lanes (lane = (ty&1)*16 + tx; xor<=8 stays in group)
#pragma unroll
        for (int off = 8; off > 0; off >>= 1)
            ssum += __shfl_xor_sync(0xffffffffu, ssum, off);

        if (tx == 0) {
            const int row = (i < 4) ? (ty * 4 + i) : (ty * 4 + 60 + i);
            g_part[nb * MTOT + m0 + row] = ssum;   // single writer per slot
        }
    }
}

// ---------------------------------------------------------------------------
// Kernel 2: scores = sum over 8 partials; e = exp(scores) (raw, per reference);
//           g_invden[b] = 1/sum_t e.   grid 32, block 256
// ---------------------------------------------------------------------------
__global__ void softmax_kernel() {
    const int b = blockIdx.x;
    __shared__ float red[256];

    float local = 0.f;
    for (int t = threadIdx.x; t < TT; t += 256) {
        const int m = b * TT + t;
        float sc = 0.f;
#pragma unroll
        for (int p = 0; p < 8; p++) sc += g_part[p * MTOT + m];
        const float e = expf(sc);
        g_esc[m] = e;
        local += e;
    }
    red[threadIdx.x] = local;
    __syncthreads();
    for (int s = 128; s > 0; s >>= 1) {
        if (threadIdx.x < s) red[threadIdx.x] += red[threadIdx.x + s];
        __syncthreads();
    }
    if (threadIdx.x == 0) g_invden[b] = 1.0f / red[0];
}

// ---------------------------------------------------------------------------
// Kernel 3: c[b][d] = (sum_t e[b][t] * h[b][t][d]) * invden[b]
// grid (4, 32), block 256 — memory-bound, one full coalesced pass over h.
// ---------------------------------------------------------------------------
__global__ void ctx_kernel(const float* __restrict__ h, float* __restrict__ out) {
    const int b = blockIdx.y;
    const int d = blockIdx.x * 256 + threadIdx.x;
    __shared__ float w[128];

    const float* hb = h + (size_t)b * TT * DD;
    float acc0 = 0.f, acc1 = 0.f;

    for (int t0 = 0; t0 < TT; t0 += 128) {
        __syncthreads();
        if (threadIdx.x < 128) w[threadIdx.x] = g_esc[b * TT + t0 + threadIdx.x];
        __syncthreads();
#pragma unroll 16
        for (int i = 0; i < 128; i += 2) {
            acc0 += w[i + 0] * hb[(size_t)(t0 + i + 0) * DD + d];
            acc1 += w[i + 1] * hb[(size_t)(t0 + i + 1) * DD + d];
        }
    }
    out[b * DD + d] = (acc0 + acc1) * g_invden[b];
}

// ---------------------------------------------------------------------------
// Launch (graph-capturable: kernels only, default stream, no allocs/syncs)
// Inputs per metadata order: s, h, W_a, U_a, v_a (all float32)
// ---------------------------------------------------------------------------
extern "C" void kernel_launch(void* const* d_in, const int* in_sizes, int n_in,
                              void* d_out, int out_size) {
    const float* s  = (const float*)d_in[0];
    const float* h  = (const float*)d_in[1];
    const float* Wa = (const float*)d_in[2];
    const float* Ua = (const float*)d_in[3];
    const float* va = (const float*)d_in[4];
    float* out = (float*)d_out;

    ws_kernel       <<<dim3(8, 32),  128>>>(s, Wa);
    score_gemm_kernel<<<dim3(8, 512), 256>>>(h, Ua, va);
    softmax_kernel  <<<32,           256>>>();
    ctx_kernel      <<<dim3(4, 32),  256>>>(h, out);
}

// round 12
// speedup vs baseline: 1.0011x; 1.0001x over previous
#include <cuda_runtime.h>
#include <math.h>

// Problem constants (fixed by the dataset)
#define BB   32
#define TT   2048
#define DD   1024
#define AA   1024
#define MTOT (BB * TT)   // 65536 rows of the big GEMM

// ---------------------------------------------------------------------------
// Scratch (static __device__ arrays: allocation-free, graph-capture safe)
// ---------------------------------------------------------------------------
__device__ float g_ws[BB * AA];        // W_a_s : [B, A]
__device__ float g_part[8 * MTOT];     // per-(n-block) score partials, deterministic
__device__ float g_esc[MTOT];          // exp(scores)
__device__ float g_invden[BB];         // 1 / sum_t exp(scores)

// ---------------------------------------------------------------------------
// Packed fp32x2 helpers (Blackwell FFMA2 — only reachable via PTX)
// ---------------------------------------------------------------------------
__device__ __forceinline__ unsigned long long pk2(float lo, float hi) {
    unsigned long long r;
    asm("mov.b64 %0, {%1, %2};" : "=l"(r) : "f"(lo), "f"(hi));
    return r;
}
__device__ __forceinline__ void up2(unsigned long long v, float& lo, float& hi) {
    asm("mov.b64 {%0, %1}, %2;" : "=f"(lo), "=f"(hi) : "l"(v));
}
__device__ __forceinline__ void fma2(unsigned long long& d,
                                     unsigned long long a,
                                     unsigned long long b) {
    asm("fma.rn.f32x2 %0, %1, %2, %3;" : "=l"(d) : "l"(a), "l"(b), "l"(d));
}

// ---------------------------------------------------------------------------
// Kernel 0: g_ws[b][a] = sum_d s[b][d] * W_a[d][a]   (tiny GEMM, 67 MFLOP)
// grid (8, 32), block 128
// ---------------------------------------------------------------------------
__global__ void ws_kernel(const float* __restrict__ s, const float* __restrict__ W) {
    __shared__ float ss[DD];
    const int b = blockIdx.y;
    const int a = blockIdx.x * 128 + threadIdx.x;

    for (int i = threadIdx.x; i < DD; i += 128) ss[i] = s[b * DD + i];
    __syncthreads();

    float a0 = 0.f, a1 = 0.f, a2 = 0.f, a3 = 0.f;
    for (int d = 0; d < DD; d += 4) {
        a0 += ss[d + 0] * W[(size_t)(d + 0) * AA + a];
        a1 += ss[d + 1] * W[(size_t)(d + 1) * AA + a];
        a2 += ss[d + 2] * W[(size_t)(d + 2) * AA + a];
        a3 += ss[d + 3] * W[(size_t)(d + 3) * AA + a];
    }
    g_ws[b * AA + a] = (a0 + a1) + (a2 + a3);
}

// ---------------------------------------------------------------------------
// Kernel 1: fused GEMM + tanh + dot(v) -> per-n-block score partials.
//
// Tile: BM=128 x BN=128 x BK=16, 256 threads, 8x8 micro-tile per thread,
// accumulated in f32x2 pairs via fma.rn.f32x2 (2 FMAs per issue slot).
// Each block owns rows [m0, m0+128) (all inside one batch b since 128 | T)
// and columns [n0, n0+128). After the K loop it collapses its tile through
// tanh(acc + ws)·v into one partial per row and writes g_part[nb][m]
// (exactly one writer per slot -> deterministic, no atomics, no zero-init).
//
// grid (8, 512), block 256
// ---------------------------------------------------------------------------
__global__ void __launch_bounds__(256, 2)
score_gemm_kernel(const float* __restrict__ h,
                  const float* __restrict__ U,
                  const float* __restrict__ v) {
    __shared__ __align__(16) float As[16][132];   // [k][m], padded: STS 2-way max
    __shared__ __align__(16) float Bs[16][128];   // [k][n]

    const int tid = threadIdx.x;
    const int nb  = blockIdx.x;          // 0..7
    const int n0  = nb * 128;
    const int m0  = blockIdx.y * 128;

    // global->shared load mapping
    const int arow = tid >> 2;           // 0..63
    const int acol = (tid & 3) << 2;     // 0,4,8,12
    const int brow = tid >> 5;           // 0..7
    const int bcol = (tid & 31) << 2;    // 0..124

    // compute mapping: 16x16 thread grid, 8x8 micro-tile (4+4 split)
    const int ty = tid >> 4;             // 0..15 -> M
    const int tx = tid & 15;             // 0..15 -> N

    const float* hA = h + (size_t)m0 * DD;

    unsigned long long acc[8][4];
#pragma unroll
    for (int i = 0; i < 8; i++)
#pragma unroll
        for (int j = 0; j < 4; j++) acc[i][j] = 0ull;

    for (int kt = 0; kt < DD; kt += 16) {
        // issue global loads first (latency overlapped with prior compute)
        float4 av0 = *reinterpret_cast<const float4*>(&hA[(size_t)arow        * DD + kt + acol]);
        float4 av1 = *reinterpret_cast<const float4*>(&hA[(size_t)(arow + 64) * DD + kt + acol]);
        float4 bv0 = *reinterpret_cast<const float4*>(&U[(size_t)(kt + brow)     * AA + n0 + bcol]);
        float4 bv1 = *reinterpret_cast<const float4*>(&U[(size_t)(kt + brow + 8) * AA + n0 + bcol]);

        __syncthreads();   // previous tile fully consumed
        As[acol + 0][arow] = av0.x;  As[acol + 1][arow] = av0.y;
        As[acol + 2][arow] = av0.z;  As[acol + 3][arow] = av0.w;
        As[acol + 0][arow + 64] = av1.x;  As[acol + 1][arow + 64] = av1.y;
        As[acol + 2][arow + 64] = av1.z;  As[acol + 3][arow + 64] = av1.w;
        *reinterpret_cast<float4*>(&Bs[brow][bcol])     = bv0;
        *reinterpret_cast<float4*>(&Bs[brow + 8][bcol]) = bv1;
        __syncthreads();

#pragma unroll
        for (int k = 0; k < 16; k++) {
            float4 a0 = *reinterpret_cast<const float4*>(&As[k][ty * 4]);
            float4 a1 = *reinterpret_cast<const float4*>(&As[k][ty * 4 + 64]);
            float4 b0 = *reinterpret_cast<const float4*>(&Bs[k][tx * 4]);
            float4 b1 = *reinterpret_cast<const float4*>(&Bs[k][tx * 4 + 64]);

            unsigned long long bb[4];
            bb[0] = pk2(b0.x, b0.y);  bb[1] = pk2(b0.z, b0.w);
            bb[2] = pk2(b1.x, b1.y);  bb[3] = pk2(b1.z, b1.w);

            float am[8] = {a0.x, a0.y, a0.z, a0.w, a1.x, a1.y, a1.z, a1.w};
#pragma unroll
            for (int i = 0; i < 8; i++) {
                unsigned long long ad = pk2(am[i], am[i]);
#pragma unroll
                for (int j = 0; j < 4; j++) fma2(acc[i][j], ad, bb[j]);
            }
        }
    }

    // ---- epilogue: tanh(acc + ws) . v -> per-row partial, reduce over tx ----
    const int b = m0 >> 11;              // T = 2048, BM=128 divides T
    const float* wsrow = g_ws + b * AA + n0;

    float wsv[8], vv[8];
#pragma unroll
    for (int jj = 0; jj < 8; jj++) {
        // columns: jj<4 -> tx*4+jj ; jj>=4 -> tx*4+64+(jj-4)
        const int col = (jj < 4) ? (tx * 4 + jj) : (tx * 4 + 60 + jj);
        wsv[jj] = wsrow[col];
        vv[jj]  = v[n0 + col];
    }

#pragma unroll
    for (int i = 0; i < 8; i++) {
        float ssum = 0.f;
#pragma unroll
        for (int j2 = 0; j2 < 4; j2++) {
            float lo, hi;
            up2(acc[i][j2], lo, hi);
            ssum += vv[2 * j2 + 0] * tanhf(lo + wsv[2 * j2 + 0]);
            ssum += vv[2 * j2 + 1] * tanhf(hi + wsv[2 * j2 + 1]);
        }
        // reduce across the 16 tx lanes (lane = (ty&1)*16 + tx; xor<=8 stays in group)
#pragma unroll
        for (int off = 8; off > 0; off >>= 1)
            ssum += __shfl_xor_sync(0xffffffffu, ssum, off);

        if (tx == 0) {
            const int row = (i < 4) ? (ty * 4 + i) : (ty * 4 + 60 + i);
            g_part[nb * MTOT + m0 + row] = ssum;   // single writer per slot
        }
    }
}

// ---------------------------------------------------------------------------
// Kernel 2: scores = sum over 8 partials; e = exp(scores) (raw, per reference);
//           g_invden[b] = 1/sum_t e.   grid 32, block 256
// ---------------------------------------------------------------------------
__global__ void softmax_kernel() {
    const int b = blockIdx.x;
    __shared__ float red[256];

    float local = 0.f;
    for (int t = threadIdx.x; t < TT; t += 256) {
        const int m = b * TT + t;
        float sc = 0.f;
#pragma unroll
        for (int p = 0; p < 8; p++) sc += g_part[p * MTOT + m];
        const float e = expf(sc);
        g_esc[m] = e;
        local += e;
    }
    red[threadIdx.x] = local;
    __syncthreads();
    for (int s = 128; s > 0; s >>= 1) {
        if (threadIdx.x < s) red[threadIdx.x] += red[threadIdx.x + s];
        __syncthreads();
    }
    if (threadIdx.x == 0) g_invden[b] = 1.0f / red[0];
}

// ---------------------------------------------------------------------------
// Kernel 3: c[b][d] = (sum_t e[b][t] * h[b][t][d]) * invden[b]
// grid (4, 32), block 256 — memory-bound, one full coalesced pass over h.
// ---------------------------------------------------------------------------
__global__ void ctx_kernel(const float* __restrict__ h, float* __restrict__ out) {
    const int b = blockIdx.y;
    const int d = blockIdx.x * 256 + threadIdx.x;
    __shared__ float w[128];

    const float* hb = h + (size_t)b * TT * DD;
    float acc0 = 0.f, acc1 = 0.f;

    for (int t0 = 0; t0 < TT; t0 += 128) {
        __syncthreads();
        if (threadIdx.x < 128) w[threadIdx.x] = g_esc[b * TT + t0 + threadIdx.x];
        __syncthreads();
#pragma unroll 16
        for (int i = 0; i < 128; i += 2) {
            acc0 += w[i + 0] * hb[(size_t)(t0 + i + 0) * DD + d];
            acc1 += w[i + 1] * hb[(size_t)(t0 + i + 1) * DD + d];
        }
    }
    out[b * DD + d] = (acc0 + acc1) * g_invden[b];
}

// ---------------------------------------------------------------------------
// Launch (graph-capturable: kernels only, default stream, no allocs/syncs)
// Inputs per metadata order: s, h, W_a, U_a, v_a (all float32)
// ---------------------------------------------------------------------------
extern "C" void kernel_launch(void* const* d_in, const int* in_sizes, int n_in,
                              void* d_out, int out_size) {
    const float* s  = (const float*)d_in[0];
    const float* h  = (const float*)d_in[1];
    const float* Wa = (const float*)d_in[2];
    const float* Ua = (const float*)d_in[3];
    const float* va = (const float*)d_in[4];
    float* out = (float*)d_out;

    ws_kernel       <<<dim3(8, 32),  128>>>(s, Wa);
    score_gemm_kernel<<<dim3(8, 512), 256>>>(h, Ua, va);
    softmax_kernel  <<<32,           256>>>();
    ctx_kernel      <<<dim3(4, 32),  256>>>(h, out);
}

// round 14
// speedup vs baseline: 2.1239x; 2.1214x over previous
#include <cuda_runtime.h>
#include <cuda_bf16.h>
#include <math.h>
#include <stdint.h>

// Problem constants (fixed by the dataset)
#define BB   32
#define TT   2048
#define DD   1024
#define AA   1024
#define MTOT (BB * TT)

// GEMM tiling: CTA 128(M) x 256(N) x 32(K), 512 threads = 16 warps (4m x 4n),
// warp tile 32x64 via mma.sync.m16n8k16 bf16 (2 m-frags x 8 n-frags).
#define BM 128
#define BN 256
#define BK 32
#define NCHUNK (DD / BK)      // 32
#define NBLK   (AA / BN)      // 4

// SMEM stage layout: rows at 80B pitch (64B data + 16B pad) -> conflict-free
// ldmatrix (8 consecutive rows start at banks 0,20,8,28,16,4,24,12).
#define PITCH   80
#define OFF_AHI 0
#define OFF_ALO (128 * PITCH)                 // 10240
#define OFF_BHI (2 * 128 * PITCH)             // 20480
#define OFF_BLO (OFF_BHI + 256 * PITCH)       // 40960
#define STAGE_BYTES (OFF_BLO + 256 * PITCH)   // 61440

#define SM_WSV   0
#define SM_VV    1024
#define SM_SP    2048
#define SM_STAGE 4096
#define SMEM_TOTAL (SM_STAGE + 2 * STAGE_BYTES)  // 126976 (1 CTA/SM)

// ---------------------------------------------------------------------------
// Scratch (static __device__ arrays: allocation-free, graph-capture safe)
// ---------------------------------------------------------------------------
__device__ __align__(16) __nv_bfloat16 g_ut_hi[(size_t)AA * DD];  // U^T [A][D]
__device__ __align__(16) __nv_bfloat16 g_ut_lo[(size_t)AA * DD];
__device__ float g_ws[BB * AA];          // W_a_s : [B, A]
__device__ float g_part[NBLK * MTOT];    // per-n-block score partials
__device__ float g_esc[MTOT];            // exp(scores)
__device__ float g_invden[BB];           // 1 / sum_t exp
__device__ float g_cpart[8 * BB * DD];   // ctx partials over T-chunks

// ---------------------------------------------------------------------------
// PTX helpers (all base-target legal: sm_75/80+ instructions only)
// ---------------------------------------------------------------------------
__device__ __forceinline__ uint32_t smem_u32(const void* p) {
    uint32_t a;
    asm("{ .reg .u64 t; cvta.to.shared.u64 t, %1; cvt.u32.u64 %0, t; }" : "=r"(a) : "l"(p));
    return a;
}

__device__ __forceinline__ void ldsm4(uint32_t* r, uint32_t addr) {
    asm volatile("ldmatrix.sync.aligned.m8n8.x4.shared.b16 {%0,%1,%2,%3}, [%4];"
        : "=r"(r[0]), "=r"(r[1]), "=r"(r[2]), "=r"(r[3]) : "r"(addr));
}

__device__ __forceinline__ void mma_bf16(float* d, const uint32_t* a, const uint32_t* b) {
    asm volatile("mma.sync.aligned.m16n8k16.row.col.f32.bf16.bf16.f32 "
        "{%0,%1,%2,%3}, {%4,%5,%6,%7}, {%8,%9}, {%0,%1,%2,%3};"
        : "+f"(d[0]), "+f"(d[1]), "+f"(d[2]), "+f"(d[3])
        : "r"(a[0]), "r"(a[1]), "r"(a[2]), "r"(a[3]), "r"(b[0]), "r"(b[1]));
}

#define CP_ASYNC16(dst, src) \
    asm volatile("cp.async.cg.shared.global [%0], [%1], 16;" :: "r"(dst), "l"(src) : "memory")
#define CP_COMMIT()  asm volatile("cp.async.commit_group;" ::: "memory")
#define CP_WAIT0()   asm volatile("cp.async.wait_group 0;" ::: "memory")

__device__ __forceinline__ unsigned pack_hi2(float x, float y,
                                             __nv_bfloat16& hx, __nv_bfloat16& hy) {
    hx = __float2bfloat16(x);
    hy = __float2bfloat16(y);
    __nv_bfloat162 p = __halves2bfloat162(hx, hy);
    return *reinterpret_cast<unsigned*>(&p);
}

// ---------------------------------------------------------------------------
// Kernel: transpose + hi/lo split U [D,A] -> Ut_hi/Ut_lo [A,D] bf16
// ---------------------------------------------------------------------------
__global__ void conv_u_kernel(const float* __restrict__ U) {
    __shared__ float t[32][33];
    const int n0 = blockIdx.x * 32, k0 = blockIdx.y * 32;
    for (int i = threadIdx.y; i < 32; i += 8)
        t[i][threadIdx.x] = U[(size_t)(k0 + i) * AA + n0 + threadIdx.x];
    __syncthreads();
    for (int i = threadIdx.y; i < 32; i += 8) {
        float x = t[threadIdx.x][i];    // U[k0+tx][n0+i]
        __nv_bfloat16 hi = __float2bfloat16(x);
        size_t o = (size_t)(n0 + i) * DD + k0 + threadIdx.x;
        g_ut_hi[o] = hi;
        g_ut_lo[o] = __float2bfloat16(x - __bfloat162float(hi));
    }
}

// ---------------------------------------------------------------------------
// Kernel: g_ws[b][a] = sum_d s[b][d] * W_a[d][a]
// ---------------------------------------------------------------------------
__global__ void ws_kernel(const float* __restrict__ s, const float* __restrict__ W) {
    __shared__ float ss[DD];
    const int b = blockIdx.y;
    const int a = blockIdx.x * 128 + threadIdx.x;
    for (int i = threadIdx.x; i < DD; i += 128) ss[i] = s[b * DD + i];
    __syncthreads();
    float a0 = 0.f, a1 = 0.f, a2 = 0.f, a3 = 0.f;
    for (int d = 0; d < DD; d += 4) {
        a0 += ss[d + 0] * W[(size_t)(d + 0) * AA + a];
        a1 += ss[d + 1] * W[(size_t)(d + 1) * AA + a];
        a2 += ss[d + 2] * W[(size_t)(d + 2) * AA + a];
        a3 += ss[d + 3] * W[(size_t)(d + 3) * AA + a];
    }
    g_ws[b * AA + a] = (a0 + a1) + (a2 + a3);
}

// ---------------------------------------------------------------------------
// GEMM loader pieces. B (bf16 hi/lo) goes via cp.async (no regs);
// A (fp32 h) staged in 8 regs, converted to bf16 hi/lo at STS time.
// ---------------------------------------------------------------------------
struct AReg { float4 x0, x1; };

__device__ __forceinline__ AReg issue_loads(uint32_t st_u32, int tid,
        const float* __restrict__ hA,
        const __nv_bfloat16* __restrict__ Bh,
        const __nv_bfloat16* __restrict__ Bl, int kt) {
#pragma unroll
    for (int i = 0; i < 2; i++) {
        const int c = tid + i * 512;       // 0..1023
        const int row = c >> 2, o = c & 3; // 256 rows x 4 x 16B
        const uint32_t off = (uint32_t)(row * PITCH + o * 16);
        CP_ASYNC16(st_u32 + OFF_BHI + off, Bh + (size_t)row * DD + kt + o * 8);
        CP_ASYNC16(st_u32 + OFF_BLO + off, Bl + (size_t)row * DD + kt + o * 8);
    }
    CP_COMMIT();
    AReg a;
    a.x0 = *reinterpret_cast<const float4*>(hA + (size_t)(tid >> 3) * DD + kt + (tid & 7) * 4);
    const int c1 = tid + 512;
    a.x1 = *reinterpret_cast<const float4*>(hA + (size_t)(c1 >> 3) * DD + kt + (c1 & 7) * 4);
    return a;
}

__device__ __forceinline__ void store_a(char* st, int tid, AReg a) {
#pragma unroll
    for (int i = 0; i < 2; i++) {
        const int c = tid + i * 512;
        const int row = c >> 3, f4 = c & 7;
        const float4 x = i ? a.x1 : a.x0;
        __nv_bfloat16 h0, h1, h2, h3;
        uint2 hv, lv;
        hv.x = pack_hi2(x.x, x.y, h0, h1);
        hv.y = pack_hi2(x.z, x.w, h2, h3);
        __nv_bfloat16 d0, d1, d2, d3;
        lv.x = pack_hi2(x.x - __bfloat162float(h0), x.y - __bfloat162float(h1), d0, d1);
        lv.y = pack_hi2(x.z - __bfloat162float(h2), x.w - __bfloat162float(h3), d2, d3);
        const int off = row * PITCH + f4 * 8;
        *reinterpret_cast<uint2*>(st + OFF_AHI + off) = hv;
        *reinterpret_cast<uint2*>(st + OFF_ALO + off) = lv;
    }
}

// ---------------------------------------------------------------------------
// Main kernel: bf16x3 HMMA GEMM (scores = h.U, fp32 accum) fused with
// tanh(.+ws).v epilogue -> per-n-block score partials.
// grid (NBLK, 512), block 512, dyn smem 126976
// ---------------------------------------------------------------------------
__global__ void __launch_bounds__(512, 1)
score_gemm(const float* __restrict__ h, const float* __restrict__ v) {
    extern __shared__ char smem[];
    float* sws = reinterpret_cast<float*>(smem + SM_WSV);
    float* sv  = reinterpret_cast<float*>(smem + SM_VV);
    float* sp  = reinterpret_cast<float*>(smem + SM_SP);

    const int tid  = threadIdx.x;
    const int lane = tid & 31, wid = tid >> 5;
    const int wm = wid & 3;        // 4 m-slabs of 32
    const int wn = wid >> 2;       // 4 n-slabs of 64
    const int nb = blockIdx.x, n0 = nb * BN;
    const int m0 = blockIdx.y * BM;
    const int b  = m0 >> 11;       // T=2048, 128 | T

    if (tid < 256) {
        sws[tid] = g_ws[b * AA + n0 + tid];
        sv[tid]  = v[n0 + tid];
    }

    const float* hA = h + (size_t)m0 * DD;
    const __nv_bfloat16* Bh = g_ut_hi + (size_t)n0 * DD;
    const __nv_bfloat16* Bl = g_ut_lo + (size_t)n0 * DD;

    float acc[2][8][4];
#pragma unroll
    for (int i = 0; i < 2; i++)
#pragma unroll
        for (int j = 0; j < 8; j++)
#pragma unroll
            for (int k = 0; k < 4; k++) acc[i][j][k] = 0.f;

    // ldmatrix per-lane address components
    const int a_row  = wm * 32 + (lane & 15);                    // + mf*16
    const int a_koff = (lane >> 4) * 16;                         // + ks*32
    const int b_row  = wn * 64 + (lane & 7) + ((lane >> 4) << 3); // + pair*16
    const int b_koff = ((lane >> 3) & 1) * 16;                   // + ks*32

    // prologue: chunk 0
    {
        AReg a0 = issue_loads(smem_u32(smem + SM_STAGE), tid, hA, Bh, Bl, 0);
        store_a(smem + SM_STAGE, tid, a0);
        CP_WAIT0();
    }
    __syncthreads();

    for (int c = 0; c < NCHUNK; c++) {
        char* cur = smem + SM_STAGE + (size_t)(c & 1) * STAGE_BYTES;
        char* nxt = smem + SM_STAGE + (size_t)((c + 1) & 1) * STAGE_BYTES;

        AReg an;
        if (c + 1 < NCHUNK)
            an = issue_loads(smem_u32(nxt), tid, hA, Bh, Bl, (c + 1) * BK);

        const uint32_t cb = smem_u32(cur);
        const uint32_t aH = cb + OFF_AHI + a_row * PITCH + a_koff;
        const uint32_t aL = cb + OFF_ALO + a_row * PITCH + a_koff;
        const uint32_t bH = cb + OFF_BHI + b_row * PITCH + b_koff;
        const uint32_t bL = cb + OFF_BLO + b_row * PITCH + b_koff;

#pragma unroll
        for (int ks = 0; ks < 2; ks++) {
            uint32_t ah[2][4], al[2][4], bb[8][2];
            ldsm4(ah[0], aH + ks * 32);
            ldsm4(ah[1], aH + 16 * PITCH + ks * 32);
            ldsm4(al[0], aL + ks * 32);
            ldsm4(al[1], aL + 16 * PITCH + ks * 32);
#pragma unroll
            for (int p = 0; p < 4; p++) {
                uint32_t r[4];
                ldsm4(r, bH + p * (16 * PITCH) + ks * 32);
                bb[2*p][0] = r[0]; bb[2*p][1] = r[1];
                bb[2*p+1][0] = r[2]; bb[2*p+1][1] = r[3];
            }
#pragma unroll
            for (int mf = 0; mf < 2; mf++)
#pragma unroll
                for (int nf = 0; nf < 8; nf++) mma_bf16(acc[mf][nf], ah[mf], bb[nf]);
#pragma unroll
            for (int mf = 0; mf < 2; mf++)
#pragma unroll
                for (int nf = 0; nf < 8; nf++) mma_bf16(acc[mf][nf], al[mf], bb[nf]);
#pragma unroll
            for (int p = 0; p < 4; p++) {
                uint32_t r[4];
                ldsm4(r, bL + p * (16 * PITCH) + ks * 32);
                bb[2*p][0] = r[0]; bb[2*p][1] = r[1];
                bb[2*p+1][0] = r[2]; bb[2*p+1][1] = r[3];
            }
#pragma unroll
            for (int mf = 0; mf < 2; mf++)
#pragma unroll
                for (int nf = 0; nf < 8; nf++) mma_bf16(acc[mf][nf], ah[mf], bb[nf]);
        }

        if (c + 1 < NCHUNK) {
            store_a(nxt, tid, an);
            CP_WAIT0();
        }
        __syncthreads();
    }

    // ---- epilogue: tanh(acc + ws) . v  ->  per-row partials -----------------
    // C frag (mf,nf): rows wm*32+mf*16+{lane/4, lane/4+8}, cols wn*64+nf*8+2(lane%4)+{0,1}
    float rp[2][2] = {{0.f, 0.f}, {0.f, 0.f}};
#pragma unroll
    for (int mf = 0; mf < 2; mf++)
#pragma unroll
        for (int nf = 0; nf < 8; nf++) {
            const int col = wn * 64 + nf * 8 + 2 * (lane & 3);
            const float w0 = sws[col], w1 = sws[col + 1];
            const float v0 = sv[col],  v1 = sv[col + 1];
            rp[mf][0] += v0 * tanhf(acc[mf][nf][0] + w0) + v1 * tanhf(acc[mf][nf][1] + w1);
            rp[mf][1] += v0 * tanhf(acc[mf][nf][2] + w0) + v1 * tanhf(acc[mf][nf][3] + w1);
        }
#pragma unroll
    for (int mf = 0; mf < 2; mf++)
#pragma unroll
        for (int rb = 0; rb < 2; rb++) {
            float ssum = rp[mf][rb];
            ssum += __shfl_xor_sync(0xffffffffu, ssum, 1);
            ssum += __shfl_xor_sync(0xffffffffu, ssum, 2);
            if ((lane & 3) == 0) {
                const int row = wm * 32 + mf * 16 + rb * 8 + (lane >> 2);
                sp[row * 4 + wn] = ssum;
            }
        }
    __syncthreads();
    if (tid < 128)
        g_part[(size_t)nb * MTOT + m0 + tid] =
            (sp[tid * 4] + sp[tid * 4 + 1]) + (sp[tid * 4 + 2] + sp[tid * 4 + 3]);
}

// ---------------------------------------------------------------------------
// Kernel: scores = sum of NBLK partials; e = exp(score) (raw, per reference);
// g_invden[b] = 1 / sum_t e.
// ---------------------------------------------------------------------------
__global__ void softmax_kernel() {
    const int b = blockIdx.x;
    __shared__ float red[256];
    float local = 0.f;
    for (int t = threadIdx.x; t < TT; t += 256) {
        const int m = b * TT + t;
        float sc = 0.f;
#pragma unroll
        for (int p = 0; p < NBLK; p++) sc += g_part[(size_t)p * MTOT + m];
        const float e = expf(sc);
        g_esc[m] = e;
        local += e;
    }
    red[threadIdx.x] = local;
    __syncthreads();
    for (int s = 128; s > 0; s >>= 1) {
        if (threadIdx.x < s) red[threadIdx.x] += red[threadIdx.x + s];
        __syncthreads();
    }
    if (threadIdx.x == 0) g_invden[b] = 1.0f / red[0];
}

// ---------------------------------------------------------------------------
// Context: c[b][d] = (sum_t e*h) * invden — T split into 8 chunks (1024 CTAs)
// then reduced. Memory-bound single pass over h.
// ---------------------------------------------------------------------------
__global__ void ctx_part_kernel(const float* __restrict__ h) {
    const int b = blockIdx.y;
    const int d = blockIdx.x * 256 + threadIdx.x;
    const int tc = blockIdx.z;
    __shared__ float w[256];
    const float* hb = h + (size_t)b * TT * DD + (size_t)tc * 256 * DD;
    w[threadIdx.x] = g_esc[b * TT + tc * 256 + threadIdx.x];
    __syncthreads();
    float a0 = 0.f, a1 = 0.f;
#pragma unroll 8
    for (int i = 0; i < 256; i += 2) {
        a0 += w[i + 0] * hb[(size_t)(i + 0) * DD + d];
        a1 += w[i + 1] * hb[(size_t)(i + 1) * DD + d];
    }
    g_cpart[((size_t)tc * BB + b) * DD + d] = a0 + a1;
}

__global__ void ctx_reduce_kernel(float* __restrict__ out) {
    const int b = blockIdx.y;
    const int d = blockIdx.x * 256 + threadIdx.x;
    float s = 0.f;
#pragma unroll
    for (int p = 0; p < 8; p++) s += g_cpart[((size_t)p * BB + b) * DD + d];
    out[b * DD + d] = s * g_invden[b];
}

// ---------------------------------------------------------------------------
// Launch (graph-capturable: kernels only)
// Inputs: s, h, W_a, U_a, v_a (all float32)
// ---------------------------------------------------------------------------
extern "C" void kernel_launch(void* const* d_in, const int* in_sizes, int n_in,
                              void* d_out, int out_size) {
    const float* s  = (const float*)d_in[0];
    const float* h  = (const float*)d_in[1];
    const float* Wa = (const float*)d_in[2];
    const float* Ua = (const float*)d_in[3];
    const float* va = (const float*)d_in[4];
    float* out = (float*)d_out;

    cudaFuncSetAttribute(score_gemm,
                         cudaFuncAttributeMaxDynamicSharedMemorySize, SMEM_TOTAL);

    conv_u_kernel    <<<dim3(32, 32), dim3(32, 8)>>>(Ua);
    ws_kernel        <<<dim3(8, 32), 128>>>(s, Wa);
    score_gemm       <<<dim3(NBLK, MTOT / BM), 512, SMEM_TOTAL>>>(h, va);
    softmax_kernel   <<<32, 256>>>();
    ctx_part_kernel  <<<dim3(4, 32, 8), 256>>>(h);
    ctx_reduce_kernel<<<dim3(4, 32), 256>>>(out);
}

// round 15
// speedup vs baseline: 3.0434x; 1.4329x over previous
#include <cuda_runtime.h>
#include <cuda_fp16.h>
#include <math.h>
#include <stdint.h>

// Problem constants (fixed by the dataset)
#define BB   32
#define TT   2048
#define DD   1024
#define AA   1024
#define MTOT (BB * TT)

// GEMM tiling: CTA 128(M) x 256(N) x 32(K), 512 threads = 16 warps (4m x 4n),
// warp tile 32x64 via mma.sync.m16n8k16 fp16 (2 m-frags x 8 n-frags).
// fp16x2 scheme: A = a_hi + a_lo (exact to ~2^-22), B = b_hi only.
// Dropped term a*b_lo ~ 2^-12 relative -> predicted rel_err ~2e-4 (<1e-3).
#define BM 128
#define BN 256
#define BK 32
#define NCHUNK (DD / BK)      // 32
#define NBLK   (AA / BN)      // 4

// SMEM stage: rows at 80B pitch (64B data + 16B pad) -> conflict-light ldmatrix.
#define PITCH   80
#define OFF_AHI 0
#define OFF_ALO (128 * PITCH)                 // 10240
#define OFF_BHI (2 * 128 * PITCH)             // 20480
#define STAGE_BYTES (OFF_BHI + 256 * PITCH)   // 40960

#define SM_WSV   0
#define SM_VV    1024
#define SM_SP    2048
#define SM_STAGE 4096
#define SMEM_TOTAL (SM_STAGE + 2 * STAGE_BYTES)  // 86016

// ---------------------------------------------------------------------------
// Scratch (static __device__ arrays: allocation-free, graph-capture safe)
// ---------------------------------------------------------------------------
__device__ __align__(16) __half g_ut_hi[(size_t)AA * DD];  // U^T [A][D] fp16
__device__ float g_ws[BB * AA];          // W_a_s : [B, A]
__device__ float g_part[NBLK * MTOT];    // per-n-block score partials
__device__ float g_esc[MTOT];            // exp(scores)
__device__ float g_invden[BB];           // 1 / sum_t exp
__device__ float g_cpart[8 * BB * DD];   // ctx partials over T-chunks

// ---------------------------------------------------------------------------
// PTX helpers (base-target legal: sm_75/80+ only)
// ---------------------------------------------------------------------------
__device__ __forceinline__ uint32_t smem_u32(const void* p) {
    uint32_t a;
    asm("{ .reg .u64 t; cvta.to.shared.u64 t, %1; cvt.u32.u64 %0, t; }" : "=r"(a) : "l"(p));
    return a;
}

__device__ __forceinline__ void ldsm4(uint32_t* r, uint32_t addr) {
    asm volatile("ldmatrix.sync.aligned.m8n8.x4.shared.b16 {%0,%1,%2,%3}, [%4];"
        : "=r"(r[0]), "=r"(r[1]), "=r"(r[2]), "=r"(r[3]) : "r"(addr));
}

__device__ __forceinline__ void mma_fp16(float* d, const uint32_t* a, const uint32_t* b) {
    asm volatile("mma.sync.aligned.m16n8k16.row.col.f32.f16.f16.f32 "
        "{%0,%1,%2,%3}, {%4,%5,%6,%7}, {%8,%9}, {%0,%1,%2,%3};"
        : "+f"(d[0]), "+f"(d[1]), "+f"(d[2]), "+f"(d[3])
        : "r"(a[0]), "r"(a[1]), "r"(a[2]), "r"(a[3]), "r"(b[0]), "r"(b[1]));
}

#define CP_ASYNC16(dst, src) \
    asm volatile("cp.async.cg.shared.global [%0], [%1], 16;" :: "r"(dst), "l"(src) : "memory")
#define CP_COMMIT()  asm volatile("cp.async.commit_group;" ::: "memory")
#define CP_WAIT0()   asm volatile("cp.async.wait_group 0;" ::: "memory")

__device__ __forceinline__ unsigned pack2h(float x, float y, __half& hx, __half& hy) {
    hx = __float2half(x);
    hy = __float2half(y);
    __half2 p = __halves2half2(hx, hy);
    return *reinterpret_cast<unsigned*>(&p);
}

// ---------------------------------------------------------------------------
// Kernel: transpose U [D,A] -> Ut_hi [A,D] fp16
// ---------------------------------------------------------------------------
__global__ void conv_u_kernel(const float* __restrict__ U) {
    __shared__ float t[32][33];
    const int n0 = blockIdx.x * 32, k0 = blockIdx.y * 32;
    for (int i = threadIdx.y; i < 32; i += 8)
        t[i][threadIdx.x] = U[(size_t)(k0 + i) * AA + n0 + threadIdx.x];
    __syncthreads();
    for (int i = threadIdx.y; i < 32; i += 8)
        g_ut_hi[(size_t)(n0 + i) * DD + k0 + threadIdx.x] = __float2half(t[threadIdx.x][i]);
}

// ---------------------------------------------------------------------------
// Kernel: g_ws[b][a] = sum_d s[b][d] * W_a[d][a]   (fp32, exact path)
// ---------------------------------------------------------------------------
__global__ void ws_kernel(const float* __restrict__ s, const float* __restrict__ W) {
    __shared__ float ss[DD];
    const int b = blockIdx.y;
    const int a = blockIdx.x * 128 + threadIdx.x;
    for (int i = threadIdx.x; i < DD; i += 128) ss[i] = s[b * DD + i];
    __syncthreads();
    float a0 = 0.f, a1 = 0.f, a2 = 0.f, a3 = 0.f;
    for (int d = 0; d < DD; d += 4) {
        a0 += ss[d + 0] * W[(size_t)(d + 0) * AA + a];
        a1 += ss[d + 1] * W[(size_t)(d + 1) * AA + a];
        a2 += ss[d + 2] * W[(size_t)(d + 2) * AA + a];
        a3 += ss[d + 3] * W[(size_t)(d + 3) * AA + a];
    }
    g_ws[b * AA + a] = (a0 + a1) + (a2 + a3);
}

// ---------------------------------------------------------------------------
// GEMM loaders. B (fp16 hi) via cp.async; A (fp32 h) staged in 8 regs and
// split to fp16 hi/lo at STS time.
// ---------------------------------------------------------------------------
struct AReg { float4 x0, x1; };

__device__ __forceinline__ AReg issue_loads(uint32_t st_u32, int tid,
        const float* __restrict__ hA,
        const __half* __restrict__ Bh, int kt) {
    // B: 256 rows x 64B = 1024 x 16B chunks -> 2 per thread
#pragma unroll
    for (int i = 0; i < 2; i++) {
        const int c = tid + i * 512;
        const int row = c >> 2, o = c & 3;
        CP_ASYNC16(st_u32 + OFF_BHI + (uint32_t)(row * PITCH + o * 16),
                   Bh + (size_t)row * DD + kt + o * 8);
    }
    CP_COMMIT();
    AReg a;
    a.x0 = *reinterpret_cast<const float4*>(hA + (size_t)(tid >> 3) * DD + kt + (tid & 7) * 4);
    const int c1 = tid + 512;
    a.x1 = *reinterpret_cast<const float4*>(hA + (size_t)(c1 >> 3) * DD + kt + (c1 & 7) * 4);
    return a;
}

__device__ __forceinline__ void store_a(char* st, int tid, AReg a) {
#pragma unroll
    for (int i = 0; i < 2; i++) {
        const int c = tid + i * 512;
        const int row = c >> 3, f4 = c & 7;
        const float4 x = i ? a.x1 : a.x0;
        __half h0, h1, h2, h3, d0, d1, d2, d3;
        uint2 hv, lv;
        hv.x = pack2h(x.x, x.y, h0, h1);
        hv.y = pack2h(x.z, x.w, h2, h3);
        lv.x = pack2h(x.x - __half2float(h0), x.y - __half2float(h1), d0, d1);
        lv.y = pack2h(x.z - __half2float(h2), x.w - __half2float(h3), d2, d3);
        const int off = row * PITCH + f4 * 8;
        *reinterpret_cast<uint2*>(st + OFF_AHI + off) = hv;
        *reinterpret_cast<uint2*>(st + OFF_ALO + off) = lv;
    }
}

// ---------------------------------------------------------------------------
// Main kernel: fp16x2 HMMA GEMM (scores = h.U, fp32 accum) fused with
// tanh(.+ws).v epilogue -> per-n-block score partials.
// grid (NBLK, 512), block 512, dyn smem 86016
// ---------------------------------------------------------------------------
__global__ void __launch_bounds__(512, 1)
score_gemm(const float* __restrict__ h, const float* __restrict__ v) {
    extern __shared__ char smem[];
    float* sws = reinterpret_cast<float*>(smem + SM_WSV);
    float* sv  = reinterpret_cast<float*>(smem + SM_VV);
    float* sp  = reinterpret_cast<float*>(smem + SM_SP);

    const int tid  = threadIdx.x;
    const int lane = tid & 31, wid = tid >> 5;
    const int wm = wid & 3;        // 4 m-slabs of 32
    const int wn = wid >> 2;       // 4 n-slabs of 64
    const int nb = blockIdx.x, n0 = nb * BN;
    const int m0 = blockIdx.y * BM;
    const int b  = m0 >> 11;       // T=2048, 128 | T

    if (tid < 256) {
        sws[tid] = g_ws[b * AA + n0 + tid];
        sv[tid]  = v[n0 + tid];
    }

    const float* hA = h + (size_t)m0 * DD;
    const __half* Bh = g_ut_hi + (size_t)n0 * DD;

    float acc[2][8][4];
#pragma unroll
    for (int i = 0; i < 2; i++)
#pragma unroll
        for (int j = 0; j < 8; j++)
#pragma unroll
            for (int k = 0; k < 4; k++) acc[i][j][k] = 0.f;

    // ldmatrix per-lane address components
    const int a_row  = wm * 32 + (lane & 15);                     // + mf*16
    const int a_koff = (lane >> 4) * 16;                          // + ks*32
    const int b_row  = wn * 64 + (lane & 7) + ((lane >> 4) << 3); // + pair*16
    const int b_koff = ((lane >> 3) & 1) * 16;                    // + ks*32

    // prologue: chunk 0
    {
        AReg a0 = issue_loads(smem_u32(smem + SM_STAGE), tid, hA, Bh, 0);
        store_a(smem + SM_STAGE, tid, a0);
        CP_WAIT0();
    }
    __syncthreads();

    for (int c = 0; c < NCHUNK; c++) {
        char* cur = smem + SM_STAGE + (size_t)(c & 1) * STAGE_BYTES;
        char* nxt = smem + SM_STAGE + (size_t)((c + 1) & 1) * STAGE_BYTES;

        AReg an;
        if (c + 1 < NCHUNK)
            an = issue_loads(smem_u32(nxt), tid, hA, Bh, (c + 1) * BK);

        const uint32_t cb = smem_u32(cur);
        const uint32_t aH = cb + OFF_AHI + a_row * PITCH + a_koff;
        const uint32_t aL = cb + OFF_ALO + a_row * PITCH + a_koff;
        const uint32_t bH = cb + OFF_BHI + b_row * PITCH + b_koff;

#pragma unroll
        for (int ks = 0; ks < 2; ks++) {
            uint32_t ah[2][4], al[2][4], bb[8][2];
            ldsm4(ah[0], aH + ks * 32);
            ldsm4(ah[1], aH + 16 * PITCH + ks * 32);
            ldsm4(al[0], aL + ks * 32);
            ldsm4(al[1], aL + 16 * PITCH + ks * 32);
#pragma unroll
            for (int p = 0; p < 4; p++) {
                uint32_t r[4];
                ldsm4(r, bH + p * (16 * PITCH) + ks * 32);
                bb[2*p][0] = r[0];   bb[2*p][1] = r[1];
                bb[2*p+1][0] = r[2]; bb[2*p+1][1] = r[3];
            }
#pragma unroll
            for (int mf = 0; mf < 2; mf++)
#pragma unroll
                for (int nf = 0; nf < 8; nf++) mma_fp16(acc[mf][nf], ah[mf], bb[nf]);
#pragma unroll
            for (int mf = 0; mf < 2; mf++)
#pragma unroll
                for (int nf = 0; nf < 8; nf++) mma_fp16(acc[mf][nf], al[mf], bb[nf]);
        }

        if (c + 1 < NCHUNK) {
            store_a(nxt, tid, an);
            CP_WAIT0();
        }
        __syncthreads();
    }

    // ---- epilogue: tanh(acc + ws) . v  ->  per-row partials -----------------
    // C frag (mf,nf): rows wm*32+mf*16+{lane/4, lane/4+8}, cols wn*64+nf*8+2(lane%4)+{0,1}
    float rp[2][2] = {{0.f, 0.f}, {0.f, 0.f}};
#pragma unroll
    for (int mf = 0; mf < 2; mf++)
#pragma unroll
        for (int nf = 0; nf < 8; nf++) {
            const int col = wn * 64 + nf * 8 + 2 * (lane & 3);
            const float w0 = sws[col], w1 = sws[col + 1];
            const float v0 = sv[col],  v1 = sv[col + 1];
            rp[mf][0] += v0 * tanhf(acc[mf][nf][0] + w0) + v1 * tanhf(acc[mf][nf][1] + w1);
            rp[mf][1] += v0 * tanhf(acc[mf][nf][2] + w0) + v1 * tanhf(acc[mf][nf][3] + w1);
        }
#pragma unroll
    for (int mf = 0; mf < 2; mf++)
#pragma unroll
        for (int rb = 0; rb < 2; rb++) {
            float ssum = rp[mf][rb];
            ssum += __shfl_xor_sync(0xffffffffu, ssum, 1);
            ssum += __shfl_xor_sync(0xffffffffu, ssum, 2);
            if ((lane & 3) == 0) {
                const int row = wm * 32 + mf * 16 + rb * 8 + (lane >> 2);
                sp[row * 4 + wn] = ssum;
            }
        }
    __syncthreads();
    if (tid < 128)
        g_part[(size_t)nb * MTOT + m0 + tid] =
            (sp[tid * 4] + sp[tid * 4 + 1]) + (sp[tid * 4 + 2] + sp[tid * 4 + 3]);
}

// ---------------------------------------------------------------------------
// Kernel: scores = sum of NBLK partials; e = exp(score) (raw, per reference);
// g_invden[b] = 1 / sum_t e.
// ---------------------------------------------------------------------------
__global__ void softmax_kernel() {
    const int b = blockIdx.x;
    __shared__ float red[256];
    float local = 0.f;
    for (int t = threadIdx.x; t < TT; t += 256) {
        const int m = b * TT + t;
        float sc = 0.f;
#pragma unroll
        for (int p = 0; p < NBLK; p++) sc += g_part[(size_t)p * MTOT + m];
        const float e = expf(sc);
        g_esc[m] = e;
        local += e;
    }
    red[threadIdx.x] = local;
    __syncthreads();
    for (int s = 128; s > 0; s >>= 1) {
        if (threadIdx.x < s) red[threadIdx.x] += red[threadIdx.x + s];
        __syncthreads();
    }
    if (threadIdx.x == 0) g_invden[b] = 1.0f / red[0];
}

// ---------------------------------------------------------------------------
// Context: c[b][d] = (sum_t e*h) * invden — T split into 8 chunks (1024 CTAs)
// then reduced. Memory-bound single pass over h.
// ---------------------------------------------------------------------------
__global__ void ctx_part_kernel(const float* __restrict__ h) {
    const int b = blockIdx.y;
    const int d = blockIdx.x * 256 + threadIdx.x;
    const int tc = blockIdx.z;
    __shared__ float w[256];
    const float* hb = h + (size_t)b * TT * DD + (size_t)tc * 256 * DD;
    w[threadIdx.x] = g_esc[b * TT + tc * 256 + threadIdx.x];
    __syncthreads();
    float a0 = 0.f, a1 = 0.f;
#pragma unroll 8
    for (int i = 0; i < 256; i += 2) {
        a0 += w[i + 0] * hb[(size_t)(i + 0) * DD + d];
        a1 += w[i + 1] * hb[(size_t)(i + 1) * DD + d];
    }
    g_cpart[((size_t)tc * BB + b) * DD + d] = a0 + a1;
}

__global__ void ctx_reduce_kernel(float* __restrict__ out) {
    const int b = blockIdx.y;
    const int d = blockIdx.x * 256 + threadIdx.x;
    float s = 0.f;
#pragma unroll
    for (int p = 0; p < 8; p++) s += g_cpart[((size_t)p * BB + b) * DD + d];
    out[b * DD + d] = s * g_invden[b];
}

// ---------------------------------------------------------------------------
// Launch (graph-capturable: kernels only)
// Inputs: s, h, W_a, U_a, v_a (all float32)
// ---------------------------------------------------------------------------
extern "C" void kernel_launch(void* const* d_in, const int* in_sizes, int n_in,
                              void* d_out, int out_size) {
    const float* s  = (const float*)d_in[0];
    const float* h  = (const float*)d_in[1];
    const float* Wa = (const float*)d_in[2];
    const float* Ua = (const float*)d_in[3];
    const float* va = (const float*)d_in[4];
    float* out = (float*)d_out;

    cudaFuncSetAttribute(score_gemm,
                         cudaFuncAttributeMaxDynamicSharedMemorySize, SMEM_TOTAL);

    conv_u_kernel    <<<dim3(32, 32), dim3(32, 8)>>>(Ua);
    ws_kernel        <<<dim3(8, 32), 128>>>(s, Wa);
    score_gemm       <<<dim3(NBLK, MTOT / BM), 512, SMEM_TOTAL>>>(h, va);
    softmax_kernel   <<<32, 256>>>();
    ctx_part_kernel  <<<dim3(4, 32, 8), 256>>>(h);
    ctx_reduce_kernel<<<dim3(4, 32), 256>>>(out);
}

// round 16
// speedup vs baseline: 4.4210x; 1.4527x over previous
#include <cuda_runtime.h>
#include <cuda_fp16.h>
#include <math.h>
#include <stdint.h>

// Problem constants (fixed by the dataset)
#define BB   32
#define TT   2048
#define DD   1024
#define AA   1024
#define MTOT (BB * TT)

// GEMM tiling: CTA 128(M) x 256(N) x 64(K), 512 threads = 16 warps (4m x 4n),
// warp tile 32x64 via mma.sync.m16n8k16 fp16 (2 m-frags x 8 n-frags).
// Single-pass fp16: A=fp16(h), B=fp16(U^T). Calibrated rel_err ~2.2e-4 (<1e-3).
#define BM 128
#define BN 256
#define BK 64
#define NCHUNK (DD / BK)      // 16
#define NBLK   (AA / BN)      // 4

// SMEM stage: rows at 144B pitch (128B data + 16B pad) -> conflict-free
// ldmatrix (+36 banks per row mod 32 = +4 -> 8 rows hit distinct bank quads).
#define PITCH   144
#define OFF_A   0
#define OFF_B   (128 * PITCH)                 // 18432
#define STAGE_BYTES (OFF_B + 256 * PITCH)     // 55296

#define SM_WSV   0
#define SM_VV    1024
#define SM_SP    2048
#define SM_STAGE 4096
#define SMEM_TOTAL (SM_STAGE + 2 * STAGE_BYTES)  // 114688 (1 CTA/SM)

// ---------------------------------------------------------------------------
// Scratch (static __device__ arrays: allocation-free, graph-capture safe)
// ---------------------------------------------------------------------------
__device__ __align__(16) __half g_ut[(size_t)AA * DD];   // U^T [A][D] fp16
__device__ float g_ws[BB * AA];          // W_a_s : [B, A]
__device__ float g_part[NBLK * MTOT];    // per-n-block score partials
__device__ float g_esc[MTOT];            // exp(scores)
__device__ float g_invden[BB];           // 1 / sum_t exp
__device__ float g_cpart[8 * BB * DD];   // ctx partials over T-chunks

// ---------------------------------------------------------------------------
// PTX helpers (base-target legal: sm_75/80+ only)
// ---------------------------------------------------------------------------
__device__ __forceinline__ uint32_t smem_u32(const void* p) {
    uint32_t a;
    asm("{ .reg .u64 t; cvta.to.shared.u64 t, %1; cvt.u32.u64 %0, t; }" : "=r"(a) : "l"(p));
    return a;
}

__device__ __forceinline__ void ldsm4(uint32_t* r, uint32_t addr) {
    asm volatile("ldmatrix.sync.aligned.m8n8.x4.shared.b16 {%0,%1,%2,%3}, [%4];"
        : "=r"(r[0]), "=r"(r[1]), "=r"(r[2]), "=r"(r[3]) : "r"(addr));
}

__device__ __forceinline__ void mma_fp16(float* d, const uint32_t* a, const uint32_t* b) {
    asm volatile("mma.sync.aligned.m16n8k16.row.col.f32.f16.f16.f32 "
        "{%0,%1,%2,%3}, {%4,%5,%6,%7}, {%8,%9}, {%0,%1,%2,%3};"
        : "+f"(d[0]), "+f"(d[1]), "+f"(d[2]), "+f"(d[3])
        : "r"(a[0]), "r"(a[1]), "r"(a[2]), "r"(a[3]), "r"(b[0]), "r"(b[1]));
}

#define CP_ASYNC16(dst, src) \
    asm volatile("cp.async.cg.shared.global [%0], [%1], 16;" :: "r"(dst), "l"(src) : "memory")
#define CP_COMMIT()  asm volatile("cp.async.commit_group;" ::: "memory")
#define CP_WAIT0()   asm volatile("cp.async.wait_group 0;" ::: "memory")

__device__ __forceinline__ uint2 cvt4h(float4 x) {
    __half2 p0 = __halves2half2(__float2half(x.x), __float2half(x.y));
    __half2 p1 = __halves2half2(__float2half(x.z), __float2half(x.w));
    uint2 r;
    r.x = *reinterpret_cast<unsigned*>(&p0);
    r.y = *reinterpret_cast<unsigned*>(&p1);
    return r;
}

// ---------------------------------------------------------------------------
// Kernel: transpose U [D,A] -> Ut [A,D] fp16
// ---------------------------------------------------------------------------
__global__ void conv_u_kernel(const float* __restrict__ U) {
    __shared__ float t[32][33];
    const int n0 = blockIdx.x * 32, k0 = blockIdx.y * 32;
    for (int i = threadIdx.y; i < 32; i += 8)
        t[i][threadIdx.x] = U[(size_t)(k0 + i) * AA + n0 + threadIdx.x];
    __syncthreads();
    for (int i = threadIdx.y; i < 32; i += 8)
        g_ut[(size_t)(n0 + i) * DD + k0 + threadIdx.x] = __float2half(t[threadIdx.x][i]);
}

// ---------------------------------------------------------------------------
// Kernel: g_ws[b][a] = sum_d s[b][d] * W_a[d][a]   (fp32, exact path)
// ---------------------------------------------------------------------------
__global__ void ws_kernel(const float* __restrict__ s, const float* __restrict__ W) {
    __shared__ float ss[DD];
    const int b = blockIdx.y;
    const int a = blockIdx.x * 128 + threadIdx.x;
    for (int i = threadIdx.x; i < DD; i += 128) ss[i] = s[b * DD + i];
    __syncthreads();
    float a0 = 0.f, a1 = 0.f, a2 = 0.f, a3 = 0.f;
    for (int d = 0; d < DD; d += 4) {
        a0 += ss[d + 0] * W[(size_t)(d + 0) * AA + a];
        a1 += ss[d + 1] * W[(size_t)(d + 1) * AA + a];
        a2 += ss[d + 2] * W[(size_t)(d + 2) * AA + a];
        a3 += ss[d + 3] * W[(size_t)(d + 3) * AA + a];
    }
    g_ws[b * AA + a] = (a0 + a1) + (a2 + a3);
}

// ---------------------------------------------------------------------------
// GEMM loaders. B (fp16) via cp.async; A (fp32 h) staged in 16 regs and
// converted to fp16 at STS time.
// A tile: 128 rows x 64 k (fp32 src) = 2048 float4 -> 4 per thread.
// B tile: 256 rows x 128B = 2048 x 16B -> 4 cp.async per thread.
// ---------------------------------------------------------------------------
struct AReg { float4 x[4]; };

__device__ __forceinline__ AReg issue_loads(uint32_t st_u32, int tid,
        const float* __restrict__ hA,
        const __half* __restrict__ Bh, int kt) {
#pragma unroll
    for (int i = 0; i < 4; i++) {
        const int c = tid + i * 512;
        const int row = c >> 3, o = c & 7;
        CP_ASYNC16(st_u32 + OFF_B + (uint32_t)(row * PITCH + o * 16),
                   Bh + (size_t)row * DD + kt + o * 8);
    }
    CP_COMMIT();
    AReg a;
#pragma unroll
    for (int i = 0; i < 4; i++) {
        const int c = tid + i * 512;
        const int row = c >> 4, u = c & 15;   // 16 float4-units per 64-elem row
        a.x[i] = *reinterpret_cast<const float4*>(hA + (size_t)row * DD + kt + u * 4);
    }
    return a;
}

__device__ __forceinline__ void store_a(char* st, int tid, AReg a) {
#pragma unroll
    for (int i = 0; i < 4; i++) {
        const int c = tid + i * 512;
        const int row = c >> 4, u = c & 15;
        *reinterpret_cast<uint2*>(st + OFF_A + row * PITCH + u * 8) = cvt4h(a.x[i]);
    }
}

// ---------------------------------------------------------------------------
// Main kernel: fp16 HMMA GEMM (scores = h.U, fp32 accum) fused with
// tanh(.+ws).v epilogue -> per-n-block score partials.
// grid (NBLK, 512), block 512, dyn smem 114688
// ---------------------------------------------------------------------------
__global__ void __launch_bounds__(512, 1)
score_gemm(const float* __restrict__ h, const float* __restrict__ v) {
    extern __shared__ char smem[];
    float* sws = reinterpret_cast<float*>(smem + SM_WSV);
    float* sv  = reinterpret_cast<float*>(smem + SM_VV);
    float* sp  = reinterpret_cast<float*>(smem + SM_SP);

    const int tid  = threadIdx.x;
    const int lane = tid & 31, wid = tid >> 5;
    const int wm = wid & 3;        // 4 m-slabs of 32
    const int wn = wid >> 2;       // 4 n-slabs of 64
    const int nb = blockIdx.x, n0 = nb * BN;
    const int m0 = blockIdx.y * BM;
    const int b  = m0 >> 11;       // T=2048, 128 | T

    if (tid < 256) {
        sws[tid] = g_ws[b * AA + n0 + tid];
        sv[tid]  = v[n0 + tid];
    }

    const float* hA = h + (size_t)m0 * DD;
    const __half* Bh = g_ut + (size_t)n0 * DD;

    float acc[2][8][4];
#pragma unroll
    for (int i = 0; i < 2; i++)
#pragma unroll
        for (int j = 0; j < 8; j++)
#pragma unroll
            for (int k = 0; k < 4; k++) acc[i][j][k] = 0.f;

    // ldmatrix per-lane address components
    const int a_row  = wm * 32 + (lane & 15);                     // + mf*16
    const int a_koff = (lane >> 4) * 16;                          // + ks*32
    const int b_row  = wn * 64 + (lane & 7) + ((lane >> 4) << 3); // + pair*16
    const int b_koff = ((lane >> 3) & 1) * 16;                    // + ks*32

    // prologue: chunk 0
    {
        AReg a0 = issue_loads(smem_u32(smem + SM_STAGE), tid, hA, Bh, 0);
        store_a(smem + SM_STAGE, tid, a0);
        CP_WAIT0();
    }
    __syncthreads();

    for (int c = 0; c < NCHUNK; c++) {
        char* cur = smem + SM_STAGE + (size_t)(c & 1) * STAGE_BYTES;
        char* nxt = smem + SM_STAGE + (size_t)((c + 1) & 1) * STAGE_BYTES;

        AReg an;
        if (c + 1 < NCHUNK)
            an = issue_loads(smem_u32(nxt), tid, hA, Bh, (c + 1) * BK);

        const uint32_t cb = smem_u32(cur);
        const uint32_t aH = cb + OFF_A + a_row * PITCH + a_koff;
        const uint32_t bH = cb + OFF_B + b_row * PITCH + b_koff;

#pragma unroll
        for (int ks = 0; ks < 4; ks++) {   // 4 K=16 steps per 64-chunk
            uint32_t ah[2][4], bb[8][2];
            ldsm4(ah[0], aH + ks * 32);
            ldsm4(ah[1], aH + 16 * PITCH + ks * 32);
#pragma unroll
            for (int p = 0; p < 4; p++) {
                uint32_t r[4];
                ldsm4(r, bH + p * (16 * PITCH) + ks * 32);
                bb[2*p][0] = r[0];   bb[2*p][1] = r[1];
                bb[2*p+1][0] = r[2]; bb[2*p+1][1] = r[3];
            }
#pragma unroll
            for (int mf = 0; mf < 2; mf++)
#pragma unroll
                for (int nf = 0; nf < 8; nf++) mma_fp16(acc[mf][nf], ah[mf], bb[nf]);
        }

        if (c + 1 < NCHUNK) {
            store_a(nxt, tid, an);
            CP_WAIT0();
        }
        __syncthreads();
    }

    // ---- epilogue: tanh(acc + ws) . v  ->  per-row partials -----------------
    // C frag (mf,nf): rows wm*32+mf*16+{lane/4, lane/4+8}, cols wn*64+nf*8+2(lane%4)+{0,1}
    float rp[2][2] = {{0.f, 0.f}, {0.f, 0.f}};
#pragma unroll
    for (int mf = 0; mf < 2; mf++)
#pragma unroll
        for (int nf = 0; nf < 8; nf++) {
            const int col = wn * 64 + nf * 8 + 2 * (lane & 3);
            const float w0 = sws[col], w1 = sws[col + 1];
            const float v0 = sv[col],  v1 = sv[col + 1];
            rp[mf][0] += v0 * tanhf(acc[mf][nf][0] + w0) + v1 * tanhf(acc[mf][nf][1] + w1);
            rp[mf][1] += v0 * tanhf(acc[mf][nf][2] + w0) + v1 * tanhf(acc[mf][nf][3] + w1);
        }
#pragma unroll
    for (int mf = 0; mf < 2; mf++)
#pragma unroll
        for (int rb = 0; rb < 2; rb++) {
            float ssum = rp[mf][rb];
            ssum += __shfl_xor_sync(0xffffffffu, ssum, 1);
            ssum += __shfl_xor_sync(0xffffffffu, ssum, 2);
            if ((lane & 3) == 0) {
                const int row = wm * 32 + mf * 16 + rb * 8 + (lane >> 2);
                sp[row * 4 + wn] = ssum;
            }
        }
    __syncthreads();
    if (tid < 128)
        g_part[(size_t)nb * MTOT + m0 + tid] =
            (sp[tid * 4] + sp[tid * 4 + 1]) + (sp[tid * 4 + 2] + sp[tid * 4 + 3]);
}

// ---------------------------------------------------------------------------
// Kernel: scores = sum of NBLK partials; e = exp(score) (raw, per reference);
// g_invden[b] = 1 / sum_t e.
// ---------------------------------------------------------------------------
__global__ void softmax_kernel() {
    const int b = blockIdx.x;
    __shared__ float red[256];
    float local = 0.f;
    for (int t = threadIdx.x; t < TT; t += 256) {
        const int m = b * TT + t;
        float sc = 0.f;
#pragma unroll
        for (int p = 0; p < NBLK; p++) sc += g_part[(size_t)p * MTOT + m];
        const float e = expf(sc);
        g_esc[m] = e;
        local += e;
    }
    red[threadIdx.x] = local;
    __syncthreads();
    for (int s = 128; s > 0; s >>= 1) {
        if (threadIdx.x < s) red[threadIdx.x] += red[threadIdx.x + s];
        __syncthreads();
    }
    if (threadIdx.x == 0) g_invden[b] = 1.0f / red[0];
}

// ---------------------------------------------------------------------------
// Context: c[b][d] = (sum_t e*h) * invden — T split into 8 chunks (1024 CTAs)
// then reduced. Memory-bound single pass over h.
// ---------------------------------------------------------------------------
__global__ void ctx_part_kernel(const float* __restrict__ h) {
    const int b = blockIdx.y;
    const int d = blockIdx.x * 256 + threadIdx.x;
    const int tc = blockIdx.z;
    __shared__ float w[256];
    const float* hb = h + (size_t)b * TT * DD + (size_t)tc * 256 * DD;
    w[threadIdx.x] = g_esc[b * TT + tc * 256 + threadIdx.x];
    __syncthreads();
    float a0 = 0.f, a1 = 0.f;
#pragma unroll 8
    for (int i = 0; i < 256; i += 2) {
        a0 += w[i + 0] * hb[(size_t)(i + 0) * DD + d];
        a1 += w[i + 1] * hb[(size_t)(i + 1) * DD + d];
    }
    g_cpart[((size_t)tc * BB + b) * DD + d] = a0 + a1;
}

__global__ void ctx_reduce_kernel(float* __restrict__ out) {
    const int b = blockIdx.y;
    const int d = blockIdx.x * 256 + threadIdx.x;
    float s = 0.f;
#pragma unroll
    for (int p = 0; p < 8; p++) s += g_cpart[((size_t)p * BB + b) * DD + d];
    out[b * DD + d] = s * g_invden[b];
}

// ---------------------------------------------------------------------------
// Launch (graph-capturable: kernels only)
// Inputs: s, h, W_a, U_a, v_a (all float32)
// ---------------------------------------------------------------------------
extern "C" void kernel_launch(void* const* d_in, const int* in_sizes, int n_in,
                              void* d_out, int out_size) {
    const float* s  = (const float*)d_in[0];
    const float* h  = (const float*)d_in[1];
    const float* Wa = (const float*)d_in[2];
    const float* Ua = (const float*)d_in[3];
    const float* va = (const float*)d_in[4];
    float* out = (float*)d_out;

    cudaFuncSetAttribute(score_gemm,
                         cudaFuncAttributeMaxDynamicSharedMemorySize, SMEM_TOTAL);

    conv_u_kernel    <<<dim3(32, 32), dim3(32, 8)>>>(Ua);
    ws_kernel        <<<dim3(8, 32), 128>>>(s, Wa);
    score_gemm       <<<dim3(NBLK, MTOT / BM), 512, SMEM_TOTAL>>>(h, va);
    softmax_kernel   <<<32, 256>>>();
    ctx_part_kernel  <<<dim3(4, 32, 8), 256>>>(h);
    ctx_reduce_kernel<<<dim3(4, 32), 256>>>(out);
}